// round 2
// baseline (speedup 1.0000x reference)
#include <cuda_runtime.h>
#include <math.h>
#include <stdint.h>

// ---------------------------------------------------------------------------
// Scale_41523743817857
// Pipeline:
//  1) g = example^2.2
//  2) t1 = conv along H (12-tap sinc, stride 2, VALID)
//  3) small = conv along W (12-tap, stride 2) -> inv gamma -> *2-1 -> s2d(2)
//     written into padded context tensor (8,66,66,64), channels 0..11
//  4) ex = example[:,5:-5,5:-5,:]*2-1 -> s2d(4) -> context channels 12..59
//  5) For i in 0..47: 3x3 SAME conv over context[..., :12+i] -> 128 ch
//     + bias, relu, dense(128->1), depth_to_space(4), *0.5+0.5
// Step 5 is a fused implicit GEMM (per-i zero-padded K chunks).
// ---------------------------------------------------------------------------

#define CTX_H 66
#define CTX_W 66
#define CTX_C 64
#define KC 16

__device__ float d_g[8 * 266 * 266 * 3];      // gamma'd example
__device__ float d_t1[8 * 128 * 266 * 3];     // after H conv
__device__ float d_ctx[8 * CTX_H * CTX_W * CTX_C]; // padded context
__device__ float d_kc[12];                    // sinc filter taps

// ---------------- filter coefficients -------------------------------------
__global__ void initCoefsK() {
    if (threadIdx.x == 0 && blockIdx.x == 0) {
        double v[12];
        double sum = 0.0;
        for (int t = 0; t < 12; t++) {
            double pos = ((double)t - 5.5) / 2.0;
            double a = sin(M_PI * pos) / (M_PI * pos);
            double p3 = pos / 3.0;
            double b = sin(M_PI * p3) / (M_PI * p3);
            double val = (double)((float)(a * b));  // match np.float32 cast
            v[t] = val;
            sum += val;
        }
        for (int t = 0; t < 12; t++) d_kc[t] = (float)(v[t] / sum);
    }
}

// ---------------- stage 1: gamma -------------------------------------------
__global__ void gammaK(const float* __restrict__ x, int n) {
    int i = blockIdx.x * blockDim.x + threadIdx.x;
    if (i < n) {
        d_g[i] = powf(x[i], 2.2f);
    }
}

// ---------------- stage 2: conv along H (stride 2, VALID) -------------------
__global__ void convHK() {
    const int n = 8 * 128 * 266 * 3;
    int idx = blockIdx.x * blockDim.x + threadIdx.x;
    if (idx >= n) return;
    float k[12];
#pragma unroll
    for (int t = 0; t < 12; t++) k[t] = d_kc[t];
    int ch = idx % 3;
    int w  = (idx / 3) % 266;
    int h  = (idx / (3 * 266)) % 128;
    int b  = idx / (3 * 266 * 128);
    const float* src = d_g + ((size_t)(b * 266 + 2 * h) * 266 + w) * 3 + ch;
    float s = 0.f;
#pragma unroll
    for (int t = 0; t < 12; t++) s += k[t] * src[(size_t)t * 266 * 3];
    d_t1[idx] = s;
}

// ---------------- zero context ---------------------------------------------
__global__ void zeroCtxK() {
    const int n4 = (8 * CTX_H * CTX_W * CTX_C) / 4;
    int i = blockIdx.x * blockDim.x + threadIdx.x;
    if (i < n4) {
        ((float4*)d_ctx)[i] = make_float4(0.f, 0.f, 0.f, 0.f);
    }
}

// ---- stage 3: conv along W (stride 2) + inv-gamma + affine + s2d(2) --------
__global__ void convWK() {
    const int n = 8 * 128 * 128 * 3;
    int idx = blockIdx.x * blockDim.x + threadIdx.x;
    if (idx >= n) return;
    float k[12];
#pragma unroll
    for (int t = 0; t < 12; t++) k[t] = d_kc[t];
    int ch = idx % 3;
    int w2 = (idx / 3) % 128;
    int h  = (idx / (3 * 128)) % 128;
    int b  = idx / (3 * 128 * 128);
    const float* src = d_t1 + ((size_t)(b * 128 + h) * 266 + 2 * w2) * 3 + ch;
    float s = 0.f;
#pragma unroll
    for (int t = 0; t < 12; t++) s += k[t] * src[t * 3];
    float v = (s > 0.f) ? powf(fmaxf(s, 1e-20f), (float)(1.0 / 2.2)) : 0.f;
    v = v * 2.f - 1.f;
    int yo = h >> 1, xo = w2 >> 1;
    int sub = ((h & 1) * 2 + (w2 & 1)) * 3 + ch;
    d_ctx[(((size_t)b * CTX_H + 1 + yo) * CTX_W + 1 + xo) * CTX_C + sub] = v;
}

// ---- stage 4: crop example, affine, s2d(4) into context ch 12..59 ----------
__global__ void exCropK(const float* __restrict__ ex) {
    const int n = 8 * 256 * 256 * 3;
    int idx = blockIdx.x * blockDim.x + threadIdx.x;
    if (idx >= n) return;
    int ch = idx % 3;
    int x  = (idx / 3) % 256;
    int y  = (idx / (3 * 256)) % 256;
    int b  = idx / (3 * 256 * 256);
    float v = ex[((size_t)(b * 266 + 5 + y) * 266 + (5 + x)) * 3 + ch] * 2.f - 1.f;
    int yo = y >> 2, xo = x >> 2;
    int sub = 12 + ((y & 3) * 4 + (x & 3)) * 3 + ch;
    d_ctx[(((size_t)b * CTX_H + 1 + yo) * CTX_W + 1 + xo) * CTX_C + sub] = v;
}

// ---- stage 5: fused implicit-GEMM conv + bias + relu + dense + d2s ---------
// Block: 256 threads. Tile: 64 pixels (16x x 4y) x 128 output channels.
// Thread (tm=tid>>4, tn=tid&15): 4 pixels x 8 channels microtile.
__global__ __launch_bounds__(256) void convPredK(
    const float* __restrict__ Wc,   // (48,3,3,59,128)
    const float* __restrict__ bc,   // (48,128)
    const float* __restrict__ Wd,   // (48,128,1)
    const float* __restrict__ bd,   // (48,1)
    float* __restrict__ out)        // (8,256,256,3)
{
    __shared__ float As[KC][64];
    __shared__ float Bs[KC][128];

    const int i = blockIdx.y;
    const int c = 12 + i;

    const int bt  = blockIdx.x;
    const int b   = bt >> 6;
    const int rem = bt & 63;
    const int ty  = rem >> 2;
    const int tx  = rem & 3;
    const int y0  = ty * 4;
    const int x0  = tx * 16;

    const int tid = threadIdx.x;
    const int tn  = tid & 15;
    const int tm  = tid >> 4;

    // A-load assignment: pixel pA = tid&63, channel group gA = tid>>6
    const int pA  = tid & 63;
    const int gA  = tid >> 6;
    const int pyA = pA >> 4;
    const int pxA = pA & 15;

    float acc[4][8];
#pragma unroll
    for (int p = 0; p < 4; p++)
#pragma unroll
        for (int j = 0; j < 8; j++) acc[p][j] = 0.f;

    const float* Wbase = Wc + (size_t)i * 9 * 59 * 128;

    for (int kyx = 0; kyx < 9; kyx++) {
        const int ky = kyx / 3;
        const int kx = kyx - ky * 3;
        // padded context: halo offset (+1) cancels conv offset (-1)
        const int gy = y0 + pyA + ky;
        const int gx = x0 + pxA + kx;
        const float* actx = d_ctx + (((size_t)b * CTX_H + gy) * CTX_W + gx) * CTX_C;
        const float* wk = Wbase + (size_t)kyx * 59 * 128;

        for (int ci0 = 0; ci0 < c; ci0 += KC) {
            const int kc = min(KC, c - ci0);

            // load A tile (padded channels 60..63 are kept at 0 by zeroCtxK;
            // channels in [c, 60) hold valid-but-unused context values that are
            // multiplied by zeroed B rows)
            float4 av = *(const float4*)(actx + ci0 + gA * 4);
            As[gA * 4 + 0][pA] = av.x;
            As[gA * 4 + 1][pA] = av.y;
            As[gA * 4 + 2][pA] = av.z;
            As[gA * 4 + 3][pA] = av.w;

            // load B tile (zero rows >= kc)
            {
                int f = tid;
                int kk = f >> 5, x4 = (f & 31) << 2;
                float4 bv = make_float4(0.f, 0.f, 0.f, 0.f);
                if (kk < kc) bv = *(const float4*)(wk + (size_t)(ci0 + kk) * 128 + x4);
                *(float4*)(&Bs[kk][x4]) = bv;
                f = tid + 256;
                kk = f >> 5; x4 = (f & 31) << 2;
                bv = make_float4(0.f, 0.f, 0.f, 0.f);
                if (kk < kc) bv = *(const float4*)(wk + (size_t)(ci0 + kk) * 128 + x4);
                *(float4*)(&Bs[kk][x4]) = bv;
            }
            __syncthreads();

#pragma unroll
            for (int k = 0; k < KC; k++) {
                float4 a4 = *(const float4*)(&As[k][tm * 4]);
                float4 b0 = *(const float4*)(&Bs[k][tn * 8]);
                float4 b1 = *(const float4*)(&Bs[k][tn * 8 + 4]);
                float a[4]  = {a4.x, a4.y, a4.z, a4.w};
                float bb[8] = {b0.x, b0.y, b0.z, b0.w, b1.x, b1.y, b1.z, b1.w};
#pragma unroll
                for (int p = 0; p < 4; p++)
#pragma unroll
                    for (int j = 0; j < 8; j++)
                        acc[p][j] = fmaf(a[p], bb[j], acc[p][j]);
            }
            __syncthreads();
        }
    }

    // epilogue: bias + relu + dense + depth_to_space + affine
    float bcv[8], wdv[8];
#pragma unroll
    for (int j = 0; j < 8; j++) {
        bcv[j] = bc[i * 128 + tn * 8 + j];
        wdv[j] = Wd[i * 128 + tn * 8 + j];
    }
    const float bdv = bd[i];
    const int r  = i / 12;
    const int ss = (i / 3) & 3;
    const int ch = i % 3;

#pragma unroll
    for (int pp = 0; pp < 4; pp++) {
        float s = 0.f;
#pragma unroll
        for (int j = 0; j < 8; j++) {
            float v = fmaxf(acc[pp][j] + bcv[j], 0.f);
            s += v * wdv[j];
        }
        // reduce across the 16 tn lanes (lanes [0..15] / [16..31] share tm)
#pragma unroll
        for (int off = 8; off; off >>= 1)
            s += __shfl_down_sync(0xffffffffu, s, off, 16);
        if (tn == 0) {
            int p  = tm * 4 + pp;
            int py = p >> 4;
            int px = p & 15;
            int yo = y0 + py;
            int xo = x0 + px;
            float val = (s + bdv) * 0.5f + 0.5f;
            out[(((size_t)b * 256 + yo * 4 + r) * 256 + (xo * 4 + ss)) * 3 + ch] = val;
        }
    }
}

// ---------------------------------------------------------------------------
extern "C" void kernel_launch(void* const* d_in, const int* in_sizes, int n_in,
                              void* d_out, int out_size) {
    const float* ex = (const float*)d_in[0];  // (8,266,266,3)
    const float* Wc = (const float*)d_in[1];  // (48,3,3,59,128)
    const float* bc = (const float*)d_in[2];  // (48,128)
    const float* Wd = (const float*)d_in[3];  // (48,128,1)
    const float* bd = (const float*)d_in[4];  // (48,1)
    float* out = (float*)d_out;               // (8,256,256,3)

    initCoefsK<<<1, 32>>>();

    const int nG = 8 * 266 * 266 * 3;
    gammaK<<<(nG + 255) / 256, 256>>>(ex, nG);

    const int nH = 8 * 128 * 266 * 3;
    convHK<<<(nH + 255) / 256, 256>>>();

    const int nZ4 = (8 * CTX_H * CTX_W * CTX_C) / 4;
    zeroCtxK<<<(nZ4 + 255) / 256, 256>>>();

    const int nW = 8 * 128 * 128 * 3;
    convWK<<<(nW + 255) / 256, 256>>>();

    const int nE = 8 * 256 * 256 * 3;
    exCropK<<<(nE + 255) / 256, 256>>>(ex);

    dim3 grid(512, 48);  // 512 pixel tiles (8 batch * 16y * 4x), 48 predictors
    convPredK<<<grid, 256>>>(Wc, bc, Wd, bd, out);
}

// round 4
// speedup vs baseline: 2.9527x; 2.9527x over previous
#include <cuda_runtime.h>
#include <cuda_bf16.h>
#include <math.h>
#include <stdint.h>

// ---------------------------------------------------------------------------
// Scale_41523743817857 — bf16-split tensor-core (mma.sync) implementation.
// Stages 1-4 build fp32 context, split into bf16 hi/lo; weights split+transposed.
// Stage 5: per (predictor i, 128-pixel tile) CTA: 9 taps x
//   { load A/B hi/lo SW128 tiles -> SMEM; 3 products x kchunks K16-steps of
//     mma.sync.m16n8k16 bf16 accumulating in fp32 registers }
//   epilogue: bias + relu + dense(128->1) + depth_to_space + affine.
// ---------------------------------------------------------------------------

#define CTX_H 66
#define CTX_W 66
#define CTX_C 64

__device__ float d_g[8 * 266 * 266 * 3];
__device__ float d_t1[8 * 128 * 266 * 3];
__device__ float d_ctx[8 * CTX_H * CTX_W * CTX_C];
__device__ float d_kc[12];
__device__ __nv_bfloat16 d_ctx_h[8 * CTX_H * CTX_W * CTX_C];
__device__ __nv_bfloat16 d_ctx_l[8 * CTX_H * CTX_W * CTX_C];
__device__ __nv_bfloat16 d_wb_h[48 * 9 * 128 * 64];
__device__ __nv_bfloat16 d_wb_l[48 * 9 * 128 * 64];

#define SW128(o) ((o) ^ (((o) >> 3) & 0x70))

__device__ __forceinline__ uint32_t smem_to_u32(const void* p) {
    uint32_t a;
    asm("{ .reg .u64 t; cvta.to.shared.u64 t, %1; cvt.u32.u64 %0, t; }"
        : "=r"(a) : "l"(p));
    return a;
}
__device__ __forceinline__ void ldsm_x4(uint32_t* r, uint32_t addr) {
    asm volatile("ldmatrix.sync.aligned.m8n8.x4.shared.b16 {%0,%1,%2,%3}, [%4];"
        : "=r"(r[0]), "=r"(r[1]), "=r"(r[2]), "=r"(r[3]) : "r"(addr));
}
__device__ __forceinline__ void mma_bf16(float* c, const uint32_t* a,
                                         const uint32_t* b) {
    asm volatile(
        "mma.sync.aligned.m16n8k16.row.col.f32.bf16.bf16.f32 "
        "{%0,%1,%2,%3}, {%4,%5,%6,%7}, {%8,%9}, {%0,%1,%2,%3};"
        : "+f"(c[0]), "+f"(c[1]), "+f"(c[2]), "+f"(c[3])
        : "r"(a[0]), "r"(a[1]), "r"(a[2]), "r"(a[3]), "r"(b[0]), "r"(b[1]));
}

// ======================= preprocessing kernels =============================
__global__ void initCoefsK() {
    if (threadIdx.x == 0 && blockIdx.x == 0) {
        double v[12]; double sum = 0.0;
        for (int t = 0; t < 12; t++) {
            double pos = ((double)t - 5.5) / 2.0;
            double a = sin(M_PI * pos) / (M_PI * pos);
            double p3 = pos / 3.0;
            double b = sin(M_PI * p3) / (M_PI * p3);
            double val = (double)((float)(a * b));
            v[t] = val; sum += val;
        }
        for (int t = 0; t < 12; t++) d_kc[t] = (float)(v[t] / sum);
    }
}
__global__ void gammaK(const float* __restrict__ x, int n) {
    int i = blockIdx.x * blockDim.x + threadIdx.x;
    if (i < n) d_g[i] = powf(x[i], 2.2f);
}
__global__ void convHK() {
    const int n = 8 * 128 * 266 * 3;
    int idx = blockIdx.x * blockDim.x + threadIdx.x;
    if (idx >= n) return;
    float k[12];
#pragma unroll
    for (int t = 0; t < 12; t++) k[t] = d_kc[t];
    int ch = idx % 3;
    int w  = (idx / 3) % 266;
    int h  = (idx / (3 * 266)) % 128;
    int b  = idx / (3 * 266 * 128);
    const float* src = d_g + ((size_t)(b * 266 + 2 * h) * 266 + w) * 3 + ch;
    float s = 0.f;
#pragma unroll
    for (int t = 0; t < 12; t++) s += k[t] * src[(size_t)t * 266 * 3];
    d_t1[idx] = s;
}
__global__ void zeroCtxK() {
    const int n4 = (8 * CTX_H * CTX_W * CTX_C) / 4;
    int i = blockIdx.x * blockDim.x + threadIdx.x;
    if (i < n4) ((float4*)d_ctx)[i] = make_float4(0.f, 0.f, 0.f, 0.f);
}
__global__ void convWK() {
    const int n = 8 * 128 * 128 * 3;
    int idx = blockIdx.x * blockDim.x + threadIdx.x;
    if (idx >= n) return;
    float k[12];
#pragma unroll
    for (int t = 0; t < 12; t++) k[t] = d_kc[t];
    int ch = idx % 3;
    int w2 = (idx / 3) % 128;
    int h  = (idx / (3 * 128)) % 128;
    int b  = idx / (3 * 128 * 128);
    const float* src = d_t1 + ((size_t)(b * 128 + h) * 266 + 2 * w2) * 3 + ch;
    float s = 0.f;
#pragma unroll
    for (int t = 0; t < 12; t++) s += k[t] * src[t * 3];
    float v = (s > 0.f) ? powf(fmaxf(s, 1e-20f), (float)(1.0 / 2.2)) : 0.f;
    v = v * 2.f - 1.f;
    int yo = h >> 1, xo = w2 >> 1;
    int sub = ((h & 1) * 2 + (w2 & 1)) * 3 + ch;
    d_ctx[(((size_t)b * CTX_H + 1 + yo) * CTX_W + 1 + xo) * CTX_C + sub] = v;
}
__global__ void exCropK(const float* __restrict__ ex) {
    const int n = 8 * 256 * 256 * 3;
    int idx = blockIdx.x * blockDim.x + threadIdx.x;
    if (idx >= n) return;
    int ch = idx % 3;
    int x  = (idx / 3) % 256;
    int y  = (idx / (3 * 256)) % 256;
    int b  = idx / (3 * 256 * 256);
    float v = ex[((size_t)(b * 266 + 5 + y) * 266 + (5 + x)) * 3 + ch] * 2.f - 1.f;
    int yo = y >> 2, xo = x >> 2;
    int sub = 12 + ((y & 3) * 4 + (x & 3)) * 3 + ch;
    d_ctx[(((size_t)b * CTX_H + 1 + yo) * CTX_W + 1 + xo) * CTX_C + sub] = v;
}
__global__ void ctxSplitK() {
    const int n = 8 * CTX_H * CTX_W * CTX_C;
    int i = blockIdx.x * blockDim.x + threadIdx.x;
    if (i >= n) return;
    float x = d_ctx[i];
    __nv_bfloat16 hi = __float2bfloat16(x);
    __nv_bfloat16 lo = __float2bfloat16(x - __bfloat162float(hi));
    d_ctx_h[i] = hi;
    d_ctx_l[i] = lo;
}
// weights -> [i][tap][n=128][ch=64] bf16 hi/lo, zero-padded for ch >= c
__global__ void wSplitK(const float* __restrict__ Wc) {
    const int n = 48 * 9 * 128 * 64;
    int idx = blockIdx.x * blockDim.x + threadIdx.x;
    if (idx >= n) return;
    int chp = idx & 63;
    int nn  = (idx >> 6) & 127;
    int tap = (idx >> 13) % 9;
    int i   = (idx >> 13) / 9;
    int c   = 12 + i;
    float v = 0.f;
    if (chp < c)
        v = Wc[((((size_t)i * 3 + tap / 3) * 3 + (tap % 3)) * 59 + chp) * 128 + nn];
    __nv_bfloat16 hi = __float2bfloat16(v);
    __nv_bfloat16 lo = __float2bfloat16(v - __bfloat162float(hi));
    d_wb_h[idx] = hi;
    d_wb_l[idx] = lo;
}

// ======================= main tensor-core kernel ===========================
#define SM_RED  0                      // 128 floats (512 B)
#define SM_BCS  512                    // 128 floats
#define SM_WDS  1024                   // 128 floats
#define SM_AH   2048
#define SM_AL   (SM_AH + 16384)
#define SM_BH   (SM_AL + 16384)
#define SM_BL   (SM_BH + 16384)
#define SM_TOTAL (SM_BL + 16384)       // 67584 bytes

__global__ __launch_bounds__(256, 2) void predMmaK(
    const float* __restrict__ bc,   // (48,128)
    const float* __restrict__ Wd,   // (48,128)
    const float* __restrict__ bd,   // (48)
    float* __restrict__ out)        // (8,256,256,3)
{
    extern __shared__ char smem[];
    uint32_t sb = smem_to_u32(smem);
    const int tid = threadIdx.x;
    const int wid = tid >> 5;
    const int lid = tid & 31;

    const int i = blockIdx.y;
    const int c = 12 + i;
    const int kchunks = (c + 15) >> 4;   // 1..4 K16 steps per tap per product
    const int nqq = kchunks * 2;         // 16B chunks per 128B row to load

    const int tile = blockIdx.x;         // b in [0,8), ty in [0,32)
    const int b  = tile >> 5;
    const int ty = tile & 31;
    const int y0 = ty * 2;               // 2 rows x 64 cols of the 64x64 grid

    if (tid < 128) {
        ((float*)(smem + SM_BCS))[tid] = bc[i * 128 + tid];
        ((float*)(smem + SM_WDS))[tid] = Wd[i * 128 + tid];
    }

    // tile-load role: row r (pixel or weight-n), 64B half hh
    const int r  = tid >> 1;
    const int hh = tid & 1;
    const int py = r >> 6;
    const int px = r & 63;

    // warp GEMM role: m-block (wid&3)*32, n-half (wid>>2)*64
    const int m0base = (wid & 3) * 32;
    const int nbase  = (wid >> 2) * 64;

    float acc[2][8][4];
#pragma unroll
    for (int mi = 0; mi < 2; mi++)
#pragma unroll
        for (int nj = 0; nj < 8; nj++)
#pragma unroll
            for (int q = 0; q < 4; q++) acc[mi][nj][q] = 0.f;

    for (int tap = 0; tap < 9; tap++) {
        const int ky = tap / 3;
        const int kx = tap - 3 * ky;
        if (tap > 0) __syncthreads();   // protect previous tiles until all warps done

        // A tile: 128 pixel rows x nqq*16 bytes (hi + lo), SW128
        {
            size_t g = ((size_t)(b * CTX_H + (y0 + py + ky)) * CTX_W + (px + kx)) * CTX_C;
            const uint4* sh = (const uint4*)(d_ctx_h + g);
            const uint4* sl = (const uint4*)(d_ctx_l + g);
#pragma unroll
            for (int q = 0; q < 4; q++) {
                int qq = hh * 4 + q;
                if (qq < nqq) {
                    uint32_t off = (uint32_t)(r * 128 + qq * 16);
                    uint32_t so = SW128(off);
                    *(uint4*)(smem + SM_AH + so) = sh[qq];
                    *(uint4*)(smem + SM_AL + so) = sl[qq];
                }
            }
        }
        // B tile: 128 n-rows x nqq*16 bytes (hi + lo), SW128
        {
            size_t g = (((size_t)i * 9 + tap) * 128 + r) * 64;
            const uint4* sh = (const uint4*)(d_wb_h + g);
            const uint4* sl = (const uint4*)(d_wb_l + g);
#pragma unroll
            for (int q = 0; q < 4; q++) {
                int qq = hh * 4 + q;
                if (qq < nqq) {
                    uint32_t off = (uint32_t)(r * 128 + qq * 16);
                    uint32_t so = SW128(off);
                    *(uint4*)(smem + SM_BH + so) = sh[qq];
                    *(uint4*)(smem + SM_BL + so) = sl[qq];
                }
            }
        }
        __syncthreads();

#pragma unroll
        for (int prod = 0; prod < 3; prod++) {
            const uint32_t sA = sb + ((prod == 2) ? SM_AL : SM_AH);
            const uint32_t sB = sb + ((prod == 1) ? SM_BL : SM_BH);
            for (int k = 0; k < kchunks; k++) {
                const int kb = k * 32;
                uint32_t bfr[4][4];
#pragma unroll
                for (int nj2 = 0; nj2 < 4; nj2++) {
                    uint32_t row = nbase + nj2 * 16 + ((lid >> 4) << 3) + (lid & 7);
                    uint32_t off = row * 128 + kb + ((lid >> 3) & 1) * 16;
                    ldsm_x4(bfr[nj2], sB + SW128(off));
                }
                uint32_t afr[2][4];
#pragma unroll
                for (int mi = 0; mi < 2; mi++) {
                    uint32_t row = m0base + mi * 16 + (lid & 15);
                    uint32_t off = row * 128 + kb + (lid >> 4) * 16;
                    ldsm_x4(afr[mi], sA + SW128(off));
                }
#pragma unroll
                for (int mi = 0; mi < 2; mi++)
#pragma unroll
                    for (int nj = 0; nj < 8; nj++)
                        mma_bf16(acc[mi][nj], afr[mi], &bfr[nj >> 1][(nj & 1) * 2]);
            }
        }
    }
    __syncthreads();

    // ---- epilogue: bias + relu + dense + cross-half reduce + d2s ----------
    const float* bcs = (const float*)(smem + SM_BCS);
    const float* wds = (const float*)(smem + SM_WDS);
    float* red = (float*)(smem + SM_RED);

    float rs[2][2];
#pragma unroll
    for (int mi = 0; mi < 2; mi++) {
#pragma unroll
        for (int h = 0; h < 2; h++) {
            float s = 0.f;
#pragma unroll
            for (int nj = 0; nj < 8; nj++) {
                int n = nbase + nj * 8 + 2 * (lid & 3);
                float v0 = acc[mi][nj][h * 2 + 0] + bcs[n];
                float v1 = acc[mi][nj][h * 2 + 1] + bcs[n + 1];
                v0 = fmaxf(v0, 0.f);
                v1 = fmaxf(v1, 0.f);
                s = fmaf(v0, wds[n], s);
                s = fmaf(v1, wds[n + 1], s);
            }
            s += __shfl_xor_sync(0xffffffffu, s, 1);
            s += __shfl_xor_sync(0xffffffffu, s, 2);
            rs[mi][h] = s;
        }
    }
    if ((wid >> 2) == 1 && (lid & 3) == 0) {
#pragma unroll
        for (int mi = 0; mi < 2; mi++)
#pragma unroll
            for (int h = 0; h < 2; h++)
                red[m0base + mi * 16 + h * 8 + (lid >> 2)] = rs[mi][h];
    }
    __syncthreads();
    if ((wid >> 2) == 0 && (lid & 3) == 0) {
        const float bdv = bd[i];
        const int rr  = i / 12;
        const int ss2 = (i / 3) & 3;
        const int chn = i % 3;
#pragma unroll
        for (int mi = 0; mi < 2; mi++)
#pragma unroll
            for (int h = 0; h < 2; h++) {
                int row = m0base + mi * 16 + h * 8 + (lid >> 2);
                float s = rs[mi][h] + red[row];
                int ppy = row >> 6;
                int ppx = row & 63;
                float val = (s + bdv) * 0.5f + 0.5f;
                out[(((size_t)b * 256 + (y0 + ppy) * 4 + rr) * 256 +
                     (ppx * 4 + ss2)) * 3 + chn] = val;
            }
    }
}

// ---------------------------------------------------------------------------
extern "C" void kernel_launch(void* const* d_in, const int* in_sizes, int n_in,
                              void* d_out, int out_size) {
    const float* ex = (const float*)d_in[0];  // (8,266,266,3)
    const float* Wc = (const float*)d_in[1];  // (48,3,3,59,128)
    const float* bc = (const float*)d_in[2];  // (48,128)
    const float* Wd = (const float*)d_in[3];  // (48,128,1)
    const float* bd = (const float*)d_in[4];  // (48,1)
    float* out = (float*)d_out;               // (8,256,256,3)

    initCoefsK<<<1, 32>>>();

    const int nG = 8 * 266 * 266 * 3;
    gammaK<<<(nG + 255) / 256, 256>>>(ex, nG);

    const int nH = 8 * 128 * 266 * 3;
    convHK<<<(nH + 255) / 256, 256>>>();

    const int nZ4 = (8 * CTX_H * CTX_W * CTX_C) / 4;
    zeroCtxK<<<(nZ4 + 255) / 256, 256>>>();

    const int nW = 8 * 128 * 128 * 3;
    convWK<<<(nW + 255) / 256, 256>>>();

    const int nE = 8 * 256 * 256 * 3;
    exCropK<<<(nE + 255) / 256, 256>>>(ex);

    const int nS = 8 * CTX_H * CTX_W * CTX_C;
    ctxSplitK<<<(nS + 255) / 256, 256>>>();

    const int nWB = 48 * 9 * 128 * 64;
    wSplitK<<<(nWB + 255) / 256, 256>>>(Wc);

    cudaFuncSetAttribute(predMmaK, cudaFuncAttributeMaxDynamicSharedMemorySize,
                         SM_TOTAL);
    dim3 grid(256, 48);
    predMmaK<<<grid, 256, SM_TOTAL>>>(bc, Wd, bd, out);
}

// round 5
// speedup vs baseline: 2.9685x; 1.0054x over previous
#include <cuda_runtime.h>
#include <cuda_bf16.h>
#include <math.h>
#include <stdint.h>

// ---------------------------------------------------------------------------
// Scale_41523743817857 — bf16-split tensor-core, cp.async double-buffered.
// Stages 1-4 build fp32 context, split into bf16 hi/lo; weights split+transposed.
// Stage 5: per (predictor i, 128-pixel tile) CTA: 9 taps, 2-stage cp.async
//   pipeline; per tap 3 split-products (AhBh+AhBl+AlBh) of m16n8k16 bf16 MMAs,
//   fp32 register accumulators. Epilogue: bias+relu+dense+d2s+affine.
// ---------------------------------------------------------------------------

#define CTX_H 66
#define CTX_W 66
#define CTX_C 64

__device__ float d_g[8 * 266 * 266 * 3];
__device__ float d_t1[8 * 128 * 266 * 3];
__device__ float d_ctx[8 * CTX_H * CTX_W * CTX_C];
__device__ float d_kc[12];
__device__ __nv_bfloat16 d_ctx_h[8 * CTX_H * CTX_W * CTX_C];
__device__ __nv_bfloat16 d_ctx_l[8 * CTX_H * CTX_W * CTX_C];
__device__ __nv_bfloat16 d_wb_h[48 * 9 * 128 * 64];
__device__ __nv_bfloat16 d_wb_l[48 * 9 * 128 * 64];

#define SW128(o) ((o) ^ (((o) >> 3) & 0x70))

__device__ __forceinline__ uint32_t smem_to_u32(const void* p) {
    uint32_t a;
    asm("{ .reg .u64 t; cvta.to.shared.u64 t, %1; cvt.u32.u64 %0, t; }"
        : "=r"(a) : "l"(p));
    return a;
}
__device__ __forceinline__ void ldsm_x4(uint32_t* r, uint32_t addr) {
    asm volatile("ldmatrix.sync.aligned.m8n8.x4.shared.b16 {%0,%1,%2,%3}, [%4];"
        : "=r"(r[0]), "=r"(r[1]), "=r"(r[2]), "=r"(r[3]) : "r"(addr));
}
__device__ __forceinline__ void mma_bf16(float* c, const uint32_t* a,
                                         const uint32_t* b) {
    asm volatile(
        "mma.sync.aligned.m16n8k16.row.col.f32.bf16.bf16.f32 "
        "{%0,%1,%2,%3}, {%4,%5,%6,%7}, {%8,%9}, {%0,%1,%2,%3};"
        : "+f"(c[0]), "+f"(c[1]), "+f"(c[2]), "+f"(c[3])
        : "r"(a[0]), "r"(a[1]), "r"(a[2]), "r"(a[3]), "r"(b[0]), "r"(b[1]));
}
#define CP_ASYNC16(dst, src) \
    asm volatile("cp.async.cg.shared.global [%0], [%1], 16;" \
        :: "r"(dst), "l"(src) : "memory")
#define CP_COMMIT() asm volatile("cp.async.commit_group;" ::: "memory")
#define CP_WAIT(n)  asm volatile("cp.async.wait_group %0;" :: "n"(n) : "memory")

// ======================= preprocessing kernels =============================
__global__ void initCoefsK() {
    if (threadIdx.x == 0 && blockIdx.x == 0) {
        double v[12]; double sum = 0.0;
        for (int t = 0; t < 12; t++) {
            double pos = ((double)t - 5.5) / 2.0;
            double a = sin(M_PI * pos) / (M_PI * pos);
            double p3 = pos / 3.0;
            double b = sin(M_PI * p3) / (M_PI * p3);
            double val = (double)((float)(a * b));
            v[t] = val; sum += val;
        }
        for (int t = 0; t < 12; t++) d_kc[t] = (float)(v[t] / sum);
    }
}
__global__ void gammaK(const float* __restrict__ x, int n) {
    int i = blockIdx.x * blockDim.x + threadIdx.x;
    if (i < n) d_g[i] = powf(x[i], 2.2f);
}
__global__ void convHK() {
    const int n = 8 * 128 * 266 * 3;
    int idx = blockIdx.x * blockDim.x + threadIdx.x;
    if (idx >= n) return;
    float k[12];
#pragma unroll
    for (int t = 0; t < 12; t++) k[t] = d_kc[t];
    int ch = idx % 3;
    int w  = (idx / 3) % 266;
    int h  = (idx / (3 * 266)) % 128;
    int b  = idx / (3 * 266 * 128);
    const float* src = d_g + ((size_t)(b * 266 + 2 * h) * 266 + w) * 3 + ch;
    float s = 0.f;
#pragma unroll
    for (int t = 0; t < 12; t++) s += k[t] * src[(size_t)t * 266 * 3];
    d_t1[idx] = s;
}
__global__ void zeroCtxK() {
    const int n4 = (8 * CTX_H * CTX_W * CTX_C) / 4;
    int i = blockIdx.x * blockDim.x + threadIdx.x;
    if (i < n4) ((float4*)d_ctx)[i] = make_float4(0.f, 0.f, 0.f, 0.f);
}
__global__ void convWK() {
    const int n = 8 * 128 * 128 * 3;
    int idx = blockIdx.x * blockDim.x + threadIdx.x;
    if (idx >= n) return;
    float k[12];
#pragma unroll
    for (int t = 0; t < 12; t++) k[t] = d_kc[t];
    int ch = idx % 3;
    int w2 = (idx / 3) % 128;
    int h  = (idx / (3 * 128)) % 128;
    int b  = idx / (3 * 128 * 128);
    const float* src = d_t1 + ((size_t)(b * 128 + h) * 266 + 2 * w2) * 3 + ch;
    float s = 0.f;
#pragma unroll
    for (int t = 0; t < 12; t++) s += k[t] * src[t * 3];
    float v = (s > 0.f) ? powf(fmaxf(s, 1e-20f), (float)(1.0 / 2.2)) : 0.f;
    v = v * 2.f - 1.f;
    int yo = h >> 1, xo = w2 >> 1;
    int sub = ((h & 1) * 2 + (w2 & 1)) * 3 + ch;
    d_ctx[(((size_t)b * CTX_H + 1 + yo) * CTX_W + 1 + xo) * CTX_C + sub] = v;
}
__global__ void exCropK(const float* __restrict__ ex) {
    const int n = 8 * 256 * 256 * 3;
    int idx = blockIdx.x * blockDim.x + threadIdx.x;
    if (idx >= n) return;
    int ch = idx % 3;
    int x  = (idx / 3) % 256;
    int y  = (idx / (3 * 256)) % 256;
    int b  = idx / (3 * 256 * 256);
    float v = ex[((size_t)(b * 266 + 5 + y) * 266 + (5 + x)) * 3 + ch] * 2.f - 1.f;
    int yo = y >> 2, xo = x >> 2;
    int sub = 12 + ((y & 3) * 4 + (x & 3)) * 3 + ch;
    d_ctx[(((size_t)b * CTX_H + 1 + yo) * CTX_W + 1 + xo) * CTX_C + sub] = v;
}
__global__ void ctxSplitK() {
    const int n = 8 * CTX_H * CTX_W * CTX_C;
    int i = blockIdx.x * blockDim.x + threadIdx.x;
    if (i >= n) return;
    float x = d_ctx[i];
    __nv_bfloat16 hi = __float2bfloat16(x);
    __nv_bfloat16 lo = __float2bfloat16(x - __bfloat162float(hi));
    d_ctx_h[i] = hi;
    d_ctx_l[i] = lo;
}
__global__ void wSplitK(const float* __restrict__ Wc) {
    const int n = 48 * 9 * 128 * 64;
    int idx = blockIdx.x * blockDim.x + threadIdx.x;
    if (idx >= n) return;
    int chp = idx & 63;
    int nn  = (idx >> 6) & 127;
    int tap = (idx >> 13) % 9;
    int i   = (idx >> 13) / 9;
    int c   = 12 + i;
    float v = 0.f;
    if (chp < c)
        v = Wc[((((size_t)i * 3 + tap / 3) * 3 + (tap % 3)) * 59 + chp) * 128 + nn];
    __nv_bfloat16 hi = __float2bfloat16(v);
    __nv_bfloat16 lo = __float2bfloat16(v - __bfloat162float(hi));
    d_wb_h[idx] = hi;
    d_wb_l[idx] = lo;
}

// ======================= main tensor-core kernel ===========================
// SMEM: RED/BCS/WDS then two 64KB stages of {AH, AL, BH, BL} 16KB tiles.
#define SM_RED   0
#define SM_BCS   512
#define SM_WDS   1024
#define SM_T0    2048
#define OFF_AH   0
#define OFF_AL   16384
#define OFF_BH   32768
#define OFF_BL   49152
#define STAGE_SZ 65536
#define SM_TOTAL (SM_T0 + 2 * STAGE_SZ)   // 133120 B

__global__ __launch_bounds__(256, 1) void predMmaK(
    const float* __restrict__ bc,   // (48,128)
    const float* __restrict__ Wd,   // (48,128)
    const float* __restrict__ bd,   // (48)
    float* __restrict__ out)        // (8,256,256,3)
{
    extern __shared__ char smem[];
    uint32_t sb = smem_to_u32(smem);
    const int tid = threadIdx.x;
    const int wid = tid >> 5;
    const int lid = tid & 31;

    const int i = blockIdx.y;
    const int c = 12 + i;
    const int kchunks = (c + 15) >> 4;   // 1..4 K16 steps per tap per product
    const int nqq = kchunks * 2;         // 16B chunks per 128B row

    const int tile = blockIdx.x;         // b in [0,8), ty in [0,32)
    const int b  = tile >> 5;
    const int ty = tile & 31;
    const int y0 = ty * 2;

    if (tid < 128) {
        ((float*)(smem + SM_BCS))[tid] = bc[i * 128 + tid];
        ((float*)(smem + SM_WDS))[tid] = Wd[i * 128 + tid];
    }

    // tile-load role: row r, 64B half hh
    const int r  = tid >> 1;
    const int hh = tid & 1;
    const int py = r >> 6;
    const int px = r & 63;

    // warp GEMM role
    const int m0base = (wid & 3) * 32;
    const int nbase  = (wid >> 2) * 64;

    float acc[2][8][4];
#pragma unroll
    for (int mi = 0; mi < 2; mi++)
#pragma unroll
        for (int nj = 0; nj < 8; nj++)
#pragma unroll
            for (int q = 0; q < 4; q++) acc[mi][nj][q] = 0.f;

    // -------- async tile loader for one tap into one stage ----------------
    auto issue_tap = [&](int tap, uint32_t stagebase) {
        const int ky = tap / 3;
        const int kx = tap - 3 * ky;
        size_t gA = ((size_t)(b * CTX_H + (y0 + py + ky)) * CTX_W + (px + kx)) * CTX_C;
        size_t gB = (((size_t)i * 9 + tap) * 128 + r) * 64;
        const char* pAh = (const char*)(d_ctx_h + gA);
        const char* pAl = (const char*)(d_ctx_l + gA);
        const char* pBh = (const char*)(d_wb_h + gB);
        const char* pBl = (const char*)(d_wb_l + gB);
#pragma unroll
        for (int q = 0; q < 4; q++) {
            int qq = hh * 4 + q;
            if (qq < nqq) {
                uint32_t so = SW128((uint32_t)(r * 128 + qq * 16));
                CP_ASYNC16(stagebase + OFF_AH + so, pAh + qq * 16);
                CP_ASYNC16(stagebase + OFF_AL + so, pAl + qq * 16);
                CP_ASYNC16(stagebase + OFF_BH + so, pBh + qq * 16);
                CP_ASYNC16(stagebase + OFF_BL + so, pBl + qq * 16);
            }
        }
        CP_COMMIT();
    };

    issue_tap(0, sb + SM_T0);

    for (int tap = 0; tap < 9; tap++) {
        const uint32_t cur = sb + SM_T0 + (uint32_t)(tap & 1) * STAGE_SZ;
        if (tap < 8) {
            issue_tap(tap + 1, sb + SM_T0 + (uint32_t)((tap + 1) & 1) * STAGE_SZ);
            CP_WAIT(1);
        } else {
            CP_WAIT(0);
        }
        __syncthreads();

        const uint32_t sAh = cur + OFF_AH;
        const uint32_t sAl = cur + OFF_AL;
        const uint32_t sBh = cur + OFF_BH;
        const uint32_t sBl = cur + OFF_BL;

        for (int k = 0; k < kchunks; k++) {
            const int kb = k * 32;
            // A fragments (hi, lo): 2 m-blocks each
            uint32_t afh[2][4], afl[2][4];
#pragma unroll
            for (int mi = 0; mi < 2; mi++) {
                uint32_t row = m0base + mi * 16 + (lid & 15);
                uint32_t so = SW128(row * 128 + kb + (lid >> 4) * 16);
                ldsm_x4(afh[mi], sAh + so);
                ldsm_x4(afl[mi], sAl + so);
            }
            // B fragments (hi, lo): 4 n-blocks each
            uint32_t bfh[4][4], bfl[4][4];
#pragma unroll
            for (int nj2 = 0; nj2 < 4; nj2++) {
                uint32_t row = nbase + nj2 * 16 + ((lid >> 4) << 3) + (lid & 7);
                uint32_t so = SW128(row * 128 + kb + ((lid >> 3) & 1) * 16);
                ldsm_x4(bfh[nj2], sBh + so);
                ldsm_x4(bfl[nj2], sBl + so);
            }
            // 3 products x 16 MMAs
#pragma unroll
            for (int mi = 0; mi < 2; mi++)
#pragma unroll
                for (int nj = 0; nj < 8; nj++) {
                    mma_bf16(acc[mi][nj], afh[mi], &bfh[nj >> 1][(nj & 1) * 2]);
                    mma_bf16(acc[mi][nj], afh[mi], &bfl[nj >> 1][(nj & 1) * 2]);
                    mma_bf16(acc[mi][nj], afl[mi], &bfh[nj >> 1][(nj & 1) * 2]);
                }
        }
        __syncthreads();
    }

    // ---- epilogue: bias + relu + dense + cross-half reduce + d2s ----------
    const float* bcs = (const float*)(smem + SM_BCS);
    const float* wds = (const float*)(smem + SM_WDS);
    float* red = (float*)(smem + SM_RED);

    float rs[2][2];
#pragma unroll
    for (int mi = 0; mi < 2; mi++) {
#pragma unroll
        for (int h = 0; h < 2; h++) {
            float s = 0.f;
#pragma unroll
            for (int nj = 0; nj < 8; nj++) {
                int n = nbase + nj * 8 + 2 * (lid & 3);
                float v0 = acc[mi][nj][h * 2 + 0] + bcs[n];
                float v1 = acc[mi][nj][h * 2 + 1] + bcs[n + 1];
                v0 = fmaxf(v0, 0.f);
                v1 = fmaxf(v1, 0.f);
                s = fmaf(v0, wds[n], s);
                s = fmaf(v1, wds[n + 1], s);
            }
            s += __shfl_xor_sync(0xffffffffu, s, 1);
            s += __shfl_xor_sync(0xffffffffu, s, 2);
            rs[mi][h] = s;
        }
    }
    if ((wid >> 2) == 1 && (lid & 3) == 0) {
#pragma unroll
        for (int mi = 0; mi < 2; mi++)
#pragma unroll
            for (int h = 0; h < 2; h++)
                red[m0base + mi * 16 + h * 8 + (lid >> 2)] = rs[mi][h];
    }
    __syncthreads();
    if ((wid >> 2) == 0 && (lid & 3) == 0) {
        const float bdv = bd[i];
        const int rr  = i / 12;
        const int ss2 = (i / 3) & 3;
        const int chn = i % 3;
#pragma unroll
        for (int mi = 0; mi < 2; mi++)
#pragma unroll
            for (int h = 0; h < 2; h++) {
                int row = m0base + mi * 16 + h * 8 + (lid >> 2);
                float s = rs[mi][h] + red[row];
                int ppy = row >> 6;
                int ppx = row & 63;
                float val = (s + bdv) * 0.5f + 0.5f;
                out[(((size_t)b * 256 + (y0 + ppy) * 4 + rr) * 256 +
                     (ppx * 4 + ss2)) * 3 + chn] = val;
            }
    }
}

// ---------------------------------------------------------------------------
extern "C" void kernel_launch(void* const* d_in, const int* in_sizes, int n_in,
                              void* d_out, int out_size) {
    const float* ex = (const float*)d_in[0];  // (8,266,266,3)
    const float* Wc = (const float*)d_in[1];  // (48,3,3,59,128)
    const float* bc = (const float*)d_in[2];  // (48,128)
    const float* Wd = (const float*)d_in[3];  // (48,128,1)
    const float* bd = (const float*)d_in[4];  // (48,1)
    float* out = (float*)d_out;               // (8,256,256,3)

    initCoefsK<<<1, 32>>>();

    const int nG = 8 * 266 * 266 * 3;
    gammaK<<<(nG + 255) / 256, 256>>>(ex, nG);

    const int nH = 8 * 128 * 266 * 3;
    convHK<<<(nH + 255) / 256, 256>>>();

    const int nZ4 = (8 * CTX_H * CTX_W * CTX_C) / 4;
    zeroCtxK<<<(nZ4 + 255) / 256, 256>>>();

    const int nW = 8 * 128 * 128 * 3;
    convWK<<<(nW + 255) / 256, 256>>>();

    const int nE = 8 * 256 * 256 * 3;
    exCropK<<<(nE + 255) / 256, 256>>>(ex);

    const int nS = 8 * CTX_H * CTX_W * CTX_C;
    ctxSplitK<<<(nS + 255) / 256, 256>>>();

    const int nWB = 48 * 9 * 128 * 64;
    wSplitK<<<(nWB + 255) / 256, 256>>>(Wc);

    cudaFuncSetAttribute(predMmaK, cudaFuncAttributeMaxDynamicSharedMemorySize,
                         SM_TOTAL);
    dim3 grid(256, 48);
    predMmaK<<<grid, 256, SM_TOTAL>>>(bc, Wd, bd, out);
}

// round 6
// speedup vs baseline: 8.1830x; 2.7566x over previous
#include <cuda_runtime.h>
#include <cuda_fp16.h>
#include <math.h>
#include <stdint.h>

// ---------------------------------------------------------------------------
// Scale_41523743817857 — single-product fp16 tensor-core implementation.
// Stages 1-4 build the context directly in fp16; weights converted+transposed
// to fp16. Stage 5: per (predictor i, 128-pixel tile) CTA: 9 taps, 2-stage
// cp.async pipeline, m16n8k16 fp16 MMAs with fp32 accumulators.
// Epilogue: bias + relu + dense(128->1) + depth_to_space + affine.
// ---------------------------------------------------------------------------

#define CTX_H 66
#define CTX_W 66
#define CTX_C 64

__device__ float d_g[8 * 266 * 266 * 3];
__device__ float d_t1[8 * 128 * 266 * 3];
__device__ float d_kc[12];
__device__ __half d_ctxf[8 * CTX_H * CTX_W * CTX_C];   // fp16 context (padded)
__device__ __half d_wf[48 * 9 * 128 * 64];             // fp16 weights [i][tap][n][ch]

#define SW128(o) ((o) ^ (((o) >> 3) & 0x70))

__device__ __forceinline__ uint32_t smem_to_u32(const void* p) {
    uint32_t a;
    asm("{ .reg .u64 t; cvta.to.shared.u64 t, %1; cvt.u32.u64 %0, t; }"
        : "=r"(a) : "l"(p));
    return a;
}
__device__ __forceinline__ void ldsm_x4(uint32_t* r, uint32_t addr) {
    asm volatile("ldmatrix.sync.aligned.m8n8.x4.shared.b16 {%0,%1,%2,%3}, [%4];"
        : "=r"(r[0]), "=r"(r[1]), "=r"(r[2]), "=r"(r[3]) : "r"(addr));
}
__device__ __forceinline__ void mma_f16(float* c, const uint32_t* a,
                                        const uint32_t* b) {
    asm volatile(
        "mma.sync.aligned.m16n8k16.row.col.f32.f16.f16.f32 "
        "{%0,%1,%2,%3}, {%4,%5,%6,%7}, {%8,%9}, {%0,%1,%2,%3};"
        : "+f"(c[0]), "+f"(c[1]), "+f"(c[2]), "+f"(c[3])
        : "r"(a[0]), "r"(a[1]), "r"(a[2]), "r"(a[3]), "r"(b[0]), "r"(b[1]));
}
#define CP_ASYNC16(dst, src) \
    asm volatile("cp.async.cg.shared.global [%0], [%1], 16;" \
        :: "r"(dst), "l"(src) : "memory")
#define CP_COMMIT() asm volatile("cp.async.commit_group;" ::: "memory")
#define CP_WAIT(n)  asm volatile("cp.async.wait_group %0;" :: "n"(n) : "memory")

// ======================= preprocessing kernels =============================
__global__ void initCoefsK() {
    if (threadIdx.x == 0 && blockIdx.x == 0) {
        double v[12]; double sum = 0.0;
        for (int t = 0; t < 12; t++) {
            double pos = ((double)t - 5.5) / 2.0;
            double a = sin(M_PI * pos) / (M_PI * pos);
            double p3 = pos / 3.0;
            double b = sin(M_PI * p3) / (M_PI * p3);
            double val = (double)((float)(a * b));
            v[t] = val; sum += val;
        }
        for (int t = 0; t < 12; t++) d_kc[t] = (float)(v[t] / sum);
    }
}
__global__ void gammaK(const float* __restrict__ x, int n) {
    int i = blockIdx.x * blockDim.x + threadIdx.x;
    if (i < n) d_g[i] = __powf(x[i], 2.2f);
}
__global__ void convHK() {
    const int n = 8 * 128 * 266 * 3;
    int idx = blockIdx.x * blockDim.x + threadIdx.x;
    if (idx >= n) return;
    float k[12];
#pragma unroll
    for (int t = 0; t < 12; t++) k[t] = d_kc[t];
    int ch = idx % 3;
    int w  = (idx / 3) % 266;
    int h  = (idx / (3 * 266)) % 128;
    int b  = idx / (3 * 266 * 128);
    const float* src = d_g + ((size_t)(b * 266 + 2 * h) * 266 + w) * 3 + ch;
    float s = 0.f;
#pragma unroll
    for (int t = 0; t < 12; t++) s += k[t] * src[(size_t)t * 266 * 3];
    d_t1[idx] = s;
}
__global__ void zeroCtxK() {
    const int n4 = (8 * CTX_H * CTX_W * CTX_C) / 4;  // 8 halves per uint4... use u32x2
    int i = blockIdx.x * blockDim.x + threadIdx.x;
    if (i < n4) ((uint2*)d_ctxf)[i] = make_uint2(0u, 0u);
}
__global__ void convWK() {
    const int n = 8 * 128 * 128 * 3;
    int idx = blockIdx.x * blockDim.x + threadIdx.x;
    if (idx >= n) return;
    float k[12];
#pragma unroll
    for (int t = 0; t < 12; t++) k[t] = d_kc[t];
    int ch = idx % 3;
    int w2 = (idx / 3) % 128;
    int h  = (idx / (3 * 128)) % 128;
    int b  = idx / (3 * 128 * 128);
    const float* src = d_t1 + ((size_t)(b * 128 + h) * 266 + 2 * w2) * 3 + ch;
    float s = 0.f;
#pragma unroll
    for (int t = 0; t < 12; t++) s += k[t] * src[t * 3];
    float v = (s > 0.f) ? __powf(fmaxf(s, 1e-20f), (float)(1.0 / 2.2)) : 0.f;
    v = v * 2.f - 1.f;
    int yo = h >> 1, xo = w2 >> 1;
    int sub = ((h & 1) * 2 + (w2 & 1)) * 3 + ch;
    d_ctxf[(((size_t)b * CTX_H + 1 + yo) * CTX_W + 1 + xo) * CTX_C + sub] =
        __float2half_rn(v);
}
__global__ void exCropK(const float* __restrict__ ex) {
    const int n = 8 * 256 * 256 * 3;
    int idx = blockIdx.x * blockDim.x + threadIdx.x;
    if (idx >= n) return;
    int ch = idx % 3;
    int x  = (idx / 3) % 256;
    int y  = (idx / (3 * 256)) % 256;
    int b  = idx / (3 * 256 * 256);
    float v = ex[((size_t)(b * 266 + 5 + y) * 266 + (5 + x)) * 3 + ch] * 2.f - 1.f;
    int yo = y >> 2, xo = x >> 2;
    int sub = 12 + ((y & 3) * 4 + (x & 3)) * 3 + ch;
    d_ctxf[(((size_t)b * CTX_H + 1 + yo) * CTX_W + 1 + xo) * CTX_C + sub] =
        __float2half_rn(v);
}
// weights -> [i][tap][n=128][ch=64] fp16, zero-padded for ch >= c
__global__ void wSplitK(const float* __restrict__ Wc) {
    const int n = 48 * 9 * 128 * 64;
    int idx = blockIdx.x * blockDim.x + threadIdx.x;
    if (idx >= n) return;
    int chp = idx & 63;
    int nn  = (idx >> 6) & 127;
    int tap = (idx >> 13) % 9;
    int i   = (idx >> 13) / 9;
    int c   = 12 + i;
    float v = 0.f;
    if (chp < c)
        v = Wc[((((size_t)i * 3 + tap / 3) * 3 + (tap % 3)) * 59 + chp) * 128 + nn];
    d_wf[idx] = __float2half_rn(v);
}

// ======================= main tensor-core kernel ===========================
// SMEM: RED/BCS/WDS then two 32KB stages of {A, B} 16KB fp16 tiles.
#define SM_RED   0
#define SM_BCS   512
#define SM_WDS   1024
#define SM_T0    2048
#define OFF_A    0
#define OFF_B    16384
#define STAGE_SZ 32768
#define SM_TOTAL (SM_T0 + 2 * STAGE_SZ)   // 67584 B

__global__ __launch_bounds__(256, 2) void predMmaK(
    const float* __restrict__ bc,   // (48,128)
    const float* __restrict__ Wd,   // (48,128)
    const float* __restrict__ bd,   // (48)
    float* __restrict__ out)        // (8,256,256,3)
{
    extern __shared__ char smem[];
    uint32_t sb = smem_to_u32(smem);
    const int tid = threadIdx.x;
    const int wid = tid >> 5;
    const int lid = tid & 31;

    const int i = blockIdx.y;
    const int c = 12 + i;
    const int kchunks = (c + 15) >> 4;   // 1..4 K16 steps per tap
    const int nqq = kchunks * 2;         // 16B chunks per 128B row

    const int tile = blockIdx.x;         // b in [0,8), ty in [0,32)
    const int b  = tile >> 5;
    const int ty = tile & 31;
    const int y0 = ty * 2;

    if (tid < 128) {
        ((float*)(smem + SM_BCS))[tid] = bc[i * 128 + tid];
        ((float*)(smem + SM_WDS))[tid] = Wd[i * 128 + tid];
    }

    // tile-load role: row r, 64B half hh
    const int r  = tid >> 1;
    const int hh = tid & 1;
    const int py = r >> 6;
    const int px = r & 63;

    // warp GEMM role
    const int m0base = (wid & 3) * 32;
    const int nbase  = (wid >> 2) * 64;

    float acc[2][8][4];
#pragma unroll
    for (int mi = 0; mi < 2; mi++)
#pragma unroll
        for (int nj = 0; nj < 8; nj++)
#pragma unroll
            for (int q = 0; q < 4; q++) acc[mi][nj][q] = 0.f;

    // -------- async tile loader for one tap into one stage ----------------
    auto issue_tap = [&](int tap, uint32_t stagebase) {
        const int ky = tap / 3;
        const int kx = tap - 3 * ky;
        size_t gA = ((size_t)(b * CTX_H + (y0 + py + ky)) * CTX_W + (px + kx)) * CTX_C;
        size_t gB = (((size_t)i * 9 + tap) * 128 + r) * 64;
        const char* pA = (const char*)(d_ctxf + gA);
        const char* pB = (const char*)(d_wf + gB);
#pragma unroll
        for (int q = 0; q < 4; q++) {
            int qq = hh * 4 + q;
            if (qq < nqq) {
                uint32_t so = SW128((uint32_t)(r * 128 + qq * 16));
                CP_ASYNC16(stagebase + OFF_A + so, pA + qq * 16);
                CP_ASYNC16(stagebase + OFF_B + so, pB + qq * 16);
            }
        }
        CP_COMMIT();
    };

    issue_tap(0, sb + SM_T0);

    for (int tap = 0; tap < 9; tap++) {
        const uint32_t cur = sb + SM_T0 + (uint32_t)(tap & 1) * STAGE_SZ;
        if (tap < 8) {
            issue_tap(tap + 1, sb + SM_T0 + (uint32_t)((tap + 1) & 1) * STAGE_SZ);
            CP_WAIT(1);
        } else {
            CP_WAIT(0);
        }
        __syncthreads();

        const uint32_t sA = cur + OFF_A;
        const uint32_t sB = cur + OFF_B;

        for (int k = 0; k < kchunks; k++) {
            const int kb = k * 32;
            uint32_t afr[2][4];
#pragma unroll
            for (int mi = 0; mi < 2; mi++) {
                uint32_t row = m0base + mi * 16 + (lid & 15);
                uint32_t so = SW128(row * 128 + kb + (lid >> 4) * 16);
                ldsm_x4(afr[mi], sA + so);
            }
            uint32_t bfr[4][4];
#pragma unroll
            for (int nj2 = 0; nj2 < 4; nj2++) {
                uint32_t row = nbase + nj2 * 16 + ((lid >> 4) << 3) + (lid & 7);
                uint32_t so = SW128(row * 128 + kb + ((lid >> 3) & 1) * 16);
                ldsm_x4(bfr[nj2], sB + so);
            }
#pragma unroll
            for (int mi = 0; mi < 2; mi++)
#pragma unroll
                for (int nj = 0; nj < 8; nj++)
                    mma_f16(acc[mi][nj], afr[mi], &bfr[nj >> 1][(nj & 1) * 2]);
        }
        __syncthreads();
    }

    // ---- epilogue: bias + relu + dense + cross-half reduce + d2s ----------
    const float* bcs = (const float*)(smem + SM_BCS);
    const float* wds = (const float*)(smem + SM_WDS);
    float* red = (float*)(smem + SM_RED);

    float rs[2][2];
#pragma unroll
    for (int mi = 0; mi < 2; mi++) {
#pragma unroll
        for (int h = 0; h < 2; h++) {
            float s = 0.f;
#pragma unroll
            for (int nj = 0; nj < 8; nj++) {
                int n = nbase + nj * 8 + 2 * (lid & 3);
                float v0 = acc[mi][nj][h * 2 + 0] + bcs[n];
                float v1 = acc[mi][nj][h * 2 + 1] + bcs[n + 1];
                v0 = fmaxf(v0, 0.f);
                v1 = fmaxf(v1, 0.f);
                s = fmaf(v0, wds[n], s);
                s = fmaf(v1, wds[n + 1], s);
            }
            s += __shfl_xor_sync(0xffffffffu, s, 1);
            s += __shfl_xor_sync(0xffffffffu, s, 2);
            rs[mi][h] = s;
        }
    }
    if ((wid >> 2) == 1 && (lid & 3) == 0) {
#pragma unroll
        for (int mi = 0; mi < 2; mi++)
#pragma unroll
            for (int h = 0; h < 2; h++)
                red[m0base + mi * 16 + h * 8 + (lid >> 2)] = rs[mi][h];
    }
    __syncthreads();
    if ((wid >> 2) == 0 && (lid & 3) == 0) {
        const float bdv = bd[i];
        const int rr  = i / 12;
        const int ss2 = (i / 3) & 3;
        const int chn = i % 3;
#pragma unroll
        for (int mi = 0; mi < 2; mi++)
#pragma unroll
            for (int h = 0; h < 2; h++) {
                int row = m0base + mi * 16 + h * 8 + (lid >> 2);
                float s = rs[mi][h] + red[row];
                int ppy = row >> 6;
                int ppx = row & 63;
                float val = (s + bdv) * 0.5f + 0.5f;
                out[(((size_t)b * 256 + (y0 + ppy) * 4 + rr) * 256 +
                     (ppx * 4 + ss2)) * 3 + chn] = val;
            }
    }
}

// ---------------------------------------------------------------------------
extern "C" void kernel_launch(void* const* d_in, const int* in_sizes, int n_in,
                              void* d_out, int out_size) {
    const float* ex = (const float*)d_in[0];  // (8,266,266,3)
    const float* Wc = (const float*)d_in[1];  // (48,3,3,59,128)
    const float* bc = (const float*)d_in[2];  // (48,128)
    const float* Wd = (const float*)d_in[3];  // (48,128,1)
    const float* bd = (const float*)d_in[4];  // (48,1)
    float* out = (float*)d_out;               // (8,256,256,3)

    initCoefsK<<<1, 32>>>();

    const int nG = 8 * 266 * 266 * 3;
    gammaK<<<(nG + 255) / 256, 256>>>(ex, nG);

    const int nH = 8 * 128 * 266 * 3;
    convHK<<<(nH + 255) / 256, 256>>>();

    const int nZ4 = (8 * CTX_H * CTX_W * CTX_C) / 4;
    zeroCtxK<<<(nZ4 + 255) / 256, 256>>>();

    const int nW = 8 * 128 * 128 * 3;
    convWK<<<(nW + 255) / 256, 256>>>();

    const int nE = 8 * 256 * 256 * 3;
    exCropK<<<(nE + 255) / 256, 256>>>(ex);

    const int nWB = 48 * 9 * 128 * 64;
    wSplitK<<<(nWB + 255) / 256, 256>>>(Wc);

    cudaFuncSetAttribute(predMmaK, cudaFuncAttributeMaxDynamicSharedMemorySize,
                         SM_TOTAL);
    dim3 grid(256, 48);
    predMmaK<<<grid, 256, SM_TOTAL>>>(bc, Wd, bd, out);
}